// round 2
// baseline (speedup 1.0000x reference)
#include <cuda_runtime.h>

#define TB 128

// fast sigmoid / tanh via MUFU exp2 + rcp; rel err ~1e-6, robust at extremes.
__device__ __forceinline__ float fsig(float x) {
    float e = __expf(-x);                     // inf for very negative x -> result 0 (correct)
    return __fdividef(1.0f, 1.0f + e);
}
__device__ __forceinline__ float ftanh(float x) {
    x = fminf(fmaxf(x, -30.0f), 30.0f);       // avoid inf/inf -> NaN
    float e = __expf(-2.0f * x);
    return __fdividef(1.0f - e, 1.0f + e);
}

extern __shared__ float s_raw[];

// LSTM core: feat = tanh(cf_W @ X + cf_b); gates; update h (regs) and c (shared).
__device__ __forceinline__ void lstm_core(
    float* __restrict__ h, const float* __restrict__ X,
    const float4* __restrict__ s_wih, const float4* __restrict__ s_whh,
    const float4* __restrict__ s_b4, const float* __restrict__ s_cf,
    float* __restrict__ s_c, float* __restrict__ s_hn, int tid)
{
    float feat[32];
#pragma unroll
    for (int m = 0; m < 32; m++) {
        float4 a  = *reinterpret_cast<const float4*>(s_cf + m * 8);
        float4 bq = *reinterpret_cast<const float4*>(s_cf + m * 8 + 4);
        float acc = bq.z;
        acc = fmaf(a.x,  X[0], acc);
        acc = fmaf(a.y,  X[1], acc);
        acc = fmaf(a.z,  X[2], acc);
        acc = fmaf(a.w,  X[3], acc);
        acc = fmaf(bq.x, X[4], acc);
        acc = fmaf(bq.y, X[5], acc);
        feat[m] = ftanh(acc);
    }
#pragma unroll 1
    for (int j = 0; j < 32; j++) {
        float4 acc = s_b4[j];
        const float4* wi = s_wih + j * 32;
        const float4* wh = s_whh + j * 32;
#pragma unroll
        for (int m = 0; m < 32; m++) {
            float4 w = wi[m];
            acc.x = fmaf(w.x, feat[m], acc.x);
            acc.y = fmaf(w.y, feat[m], acc.y);
            acc.z = fmaf(w.z, feat[m], acc.z);
            acc.w = fmaf(w.w, feat[m], acc.w);
        }
#pragma unroll
        for (int m = 0; m < 32; m++) {
            float4 w = wh[m];
            acc.x = fmaf(w.x, h[m], acc.x);
            acc.y = fmaf(w.y, h[m], acc.y);
            acc.z = fmaf(w.z, h[m], acc.z);
            acc.w = fmaf(w.w, h[m], acc.w);
        }
        // gate order: i, f, g, o
        float ig = fsig(acc.x), fg = fsig(acc.y);
        float gg = ftanh(acc.z), og = fsig(acc.w);
        float cj = s_c[j * TB + tid];
        cj = fmaf(fg, cj, ig * gg);
        s_c[j * TB + tid]  = cj;
        s_hn[j * TB + tid] = og * ftanh(cj);
    }
#pragma unroll
    for (int m = 0; m < 32; m++) h[m] = s_hn[m * TB + tid];
}

__global__ void __launch_bounds__(TB, 3) kalman_lstm_kernel(
    const float* __restrict__ hist,
    const float* __restrict__ p_psx, const float* __restrict__ p_psy,
    const float* __restrict__ p_vsx, const float* __restrict__ p_vsy,
    const float* __restrict__ p_asx, const float* __restrict__ p_asy,
    const float* __restrict__ p_jerk, const float* __restrict__ p_coefG,
    const float* __restrict__ p_GR,
    const float* __restrict__ cfW, const float* __restrict__ cfb,
    const float* __restrict__ Wih, const float* __restrict__ Whh,
    const float* __restrict__ bih, const float* __restrict__ bhh,
    const float* __restrict__ coW, const float* __restrict__ cob,
    float* __restrict__ out,
    int B, int T, int LP)
{
    // shared layout (floats): wih 4096 | whh 4096 | b4 128 | co 128 | cf 256 | cob+pad 16 | c 32*TB | hn 32*TB
    float4* s_wih = reinterpret_cast<float4*>(s_raw);
    float4* s_whh = s_wih + 1024;
    float4* s_b4  = s_whh + 1024;
    float4* s_co  = s_b4 + 32;
    float*  s_cf  = reinterpret_cast<float*>(s_co + 32);
    float*  s_cob = s_cf + 256;
    float*  s_c   = s_cob + 16;
    float*  s_hn  = s_c + 32 * TB;

    const int tid = threadIdx.x;

    // Stage weights: gate-interleaved float4 (gates i,f,g,o for (j,m) adjacent)
    for (int idx = tid; idx < 1024; idx += TB) {
        int j = idx >> 5, m = idx & 31;
        s_wih[idx] = make_float4(Wih[(j) * 32 + m],      Wih[(32 + j) * 32 + m],
                                 Wih[(64 + j) * 32 + m], Wih[(96 + j) * 32 + m]);
        s_whh[idx] = make_float4(Whh[(j) * 32 + m],      Whh[(32 + j) * 32 + m],
                                 Whh[(64 + j) * 32 + m], Whh[(96 + j) * 32 + m]);
    }
    if (tid < 32) {
        int j = tid;
        s_b4[j] = make_float4(bih[j] + bhh[j],           bih[32 + j] + bhh[32 + j],
                              bih[64 + j] + bhh[64 + j], bih[96 + j] + bhh[96 + j]);
        s_co[j] = make_float4(coW[j], coW[32 + j], coW[64 + j], coW[96 + j]);
#pragma unroll
        for (int k = 0; k < 6; k++) s_cf[j * 8 + k] = cfW[j * 6 + k];
        s_cf[j * 8 + 6] = cfb[j];
        s_cf[j * 8 + 7] = 0.0f;
    }
    if (tid < 4) s_cob[tid] = cob[tid];
    __syncthreads();

    const int b = blockIdx.x * TB + tid;
    if (b >= B) return;

    const float dt = 0.2f, hd2 = 0.02f;
    const float g0 = (float)(0.2 * 0.2 * 0.2 / 6.0);  // dt^3/6
    const float g1 = 0.02f;                            // dt^2/2
    const float g2 = 0.2f;                             // dt

    float tg[6];
#pragma unroll
    for (int i = 0; i < 6; i++) tg[i] = tanhf(p_coefG[i]);
    const float jk0 = p_jerk[0], jk1 = p_jerk[1];
    // history-phase process noise vectors (block-diag outer products)
    const float Ghx0 = g0 * tg[0] * jk0, Ghx1 = g1 * tg[1] * jk0, Ghx2 = g2 * tg[2] * jk0;
    const float Ghy0 = g0 * tg[3] * jk1, Ghy1 = g1 * tg[4] * jk1, Ghy2 = g2 * tg[5] * jk1;
    // prediction-phase G*tanhG
    const float gt0 = g0 * tg[0], gt1 = g1 * tg[1], gt2 = g2 * tg[2];
    const float gt3 = g0 * tg[3], gt4 = g1 * tg[4], gt5 = g2 * tg[5];
    const float gr0 = p_GR[0], gr1 = p_GR[1];
    const float R00 = gr0 * gr0, R01 = gr0 * gr1, R11 = gr1 * gr1;

    // ---- Kalman init ----
    float z0x = hist[(size_t)b * 2 + 0],            z0y = hist[(size_t)b * 2 + 1];
    float z1x = hist[((size_t)B + b) * 2 + 0],      z1y = hist[((size_t)B + b) * 2 + 1];
    float X[6];
    X[0] = z0x; X[1] = (z1x - z0x) / dt; X[2] = 0.0f;
    X[3] = (z1y - z0y) / dt; X[4] = 0.0f; X[5] = 0.0f;   // X[3] overwritten with Vy, per reference

    float P[6][6];
#pragma unroll
    for (int i = 0; i < 6; i++)
#pragma unroll
        for (int j = 0; j < 6; j++) P[i][j] = 0.0f;
    {
        float d0 = p_psx[0], d1 = p_vsx[0], d2 = p_asx[0];
        float d3 = p_psy[0], d4 = p_vsy[0], d5 = p_asy[0];
        P[0][0] = d0 * d0; P[1][1] = d1 * d1; P[2][2] = d2 * d2;
        P[3][3] = d3 * d3; P[4][4] = d4 * d4; P[5][5] = d5 * d5;
    }

    float h[32];
#pragma unroll
    for (int m = 0; m < 32; m++) { h[m] = 0.0f; s_c[m * TB + tid] = 0.0f; }

    // ================= history filtering =================
#pragma unroll 1
    for (int t = 1; t < T; t++) {
        lstm_core(h, X, s_wih, s_whh, s_b4, s_cf, s_c, s_hn, tid);

        // X = F X
        {
            float x0 = X[0] + dt * X[1] + hd2 * X[2];
            float x1 = X[1] + dt * X[2];
            float x3 = X[3] + dt * X[4] + hd2 * X[5];
            float x4 = X[4] + dt * X[5];
            X[0] = x0; X[1] = x1; X[3] = x3; X[4] = x4;
        }
        // P = F P F^T + Q_hist  (sparse F: row then col axpys)
#pragma unroll
        for (int cc = 0; cc < 6; cc++) {
            P[0][cc] += dt * P[1][cc] + hd2 * P[2][cc];
            P[1][cc] += dt * P[2][cc];
            P[3][cc] += dt * P[4][cc] + hd2 * P[5][cc];
            P[4][cc] += dt * P[5][cc];
        }
#pragma unroll
        for (int r = 0; r < 6; r++) {
            P[r][0] += dt * P[r][1] + hd2 * P[r][2];
            P[r][1] += dt * P[r][2];
            P[r][3] += dt * P[r][4] + hd2 * P[r][5];
            P[r][4] += dt * P[r][5];
        }
        {
            float gx[3] = {Ghx0, Ghx1, Ghx2}, gy[3] = {Ghy0, Ghy1, Ghy2};
#pragma unroll
            for (int a = 0; a < 3; a++)
#pragma unroll
                for (int bb = 0; bb < 3; bb++) {
                    P[a][bb]         += gx[a] * gx[bb];
                    P[3 + a][3 + bb] += gy[a] * gy[bb];
                }
        }
        // measurement update
        float zx = hist[((size_t)t * B + b) * 2 + 0];
        float zy = hist[((size_t)t * B + b) * 2 + 1];
        float yx = zx - X[0], yy = zy - X[3];
        float S00 = P[0][0] + R00, S01 = P[0][3] + R01;
        float S10 = P[3][0] + R01, S11 = P[3][3] + R11;
        float rdet = 1.0f / (S00 * S11 - S01 * S10);
        float si00 =  S11 * rdet, si01 = -S01 * rdet;
        float si10 = -S10 * rdet, si11 =  S00 * rdet;
        float K0[6], K1[6];
#pragma unroll
        for (int i = 0; i < 6; i++) {
            K0[i] = P[i][0] * si00 + P[i][3] * si10;
            K1[i] = P[i][0] * si01 + P[i][3] * si11;
        }
#pragma unroll
        for (int i = 0; i < 6; i++) X[i] += K0[i] * yx + K1[i] * yy;
        // Joseph form: P = (I-KH) P (I-KH)^T + K R K^T
        float r0[6], r3[6];
#pragma unroll
        for (int j = 0; j < 6; j++) { r0[j] = P[0][j]; r3[j] = P[3][j]; }
#pragma unroll
        for (int i = 0; i < 6; i++)
#pragma unroll
            for (int j = 0; j < 6; j++) P[i][j] -= K0[i] * r0[j] + K1[i] * r3[j];
        float q0[6], q3[6];
#pragma unroll
        for (int i = 0; i < 6; i++) { q0[i] = P[i][0]; q3[i] = P[i][3]; }
#pragma unroll
        for (int i = 0; i < 6; i++)
#pragma unroll
            for (int j = 0; j < 6; j++) P[i][j] -= q0[i] * K0[j] + q3[i] * K1[j];
#pragma unroll
        for (int i = 0; i < 6; i++) {
            float kr0 = K0[i] * R00 + K1[i] * R01;
            float kr1 = K0[i] * R01 + K1[i] * R11;
#pragma unroll
            for (int j = 0; j < 6; j++) P[i][j] += kr0 * K0[j] + kr1 * K1[j];
        }
    }

    // ================= prediction =================
#pragma unroll 1
    for (int t = 0; t < LP; t++) {
        lstm_core(h, X, s_wih, s_whh, s_b4, s_cf, s_c, s_hn, tid);
        // command = h @ co_W^T + co_b
        float cm0 = s_cob[0], cm1 = s_cob[1], cm2 = s_cob[2], cm3 = s_cob[3];
#pragma unroll
        for (int m = 0; m < 32; m++) {
            float4 w = s_co[m];
            cm0 = fmaf(w.x, h[m], cm0);
            cm1 = fmaf(w.y, h[m], cm1);
            cm2 = fmaf(w.z, h[m], cm2);
            cm3 = fmaf(w.w, h[m], cm3);
        }
        // X = F X + B cmd[:2]
        {
            float x0 = X[0] + dt * X[1] + hd2 * X[2] + g0 * cm0;
            float x1 = X[1] + dt * X[2] + g1 * cm0;
            float x2 = X[2] + g2 * cm0;
            float x3 = X[3] + dt * X[4] + hd2 * X[5] + g0 * cm1;
            float x4 = X[4] + dt * X[5] + g1 * cm1;
            float x5 = X[5] + g2 * cm1;
            X[0] = x0; X[1] = x1; X[2] = x2; X[3] = x3; X[4] = x4; X[5] = x5;
        }
        float Gs[6] = {gt0 * cm2, gt1 * cm2, gt2 * cm2, gt3 * cm3, gt4 * cm3, gt5 * cm3};
        // P = F P F^T + Gs Gs^T
#pragma unroll
        for (int cc = 0; cc < 6; cc++) {
            P[0][cc] += dt * P[1][cc] + hd2 * P[2][cc];
            P[1][cc] += dt * P[2][cc];
            P[3][cc] += dt * P[4][cc] + hd2 * P[5][cc];
            P[4][cc] += dt * P[5][cc];
        }
#pragma unroll
        for (int r = 0; r < 6; r++) {
            P[r][0] += dt * P[r][1] + hd2 * P[r][2];
            P[r][1] += dt * P[r][2];
            P[r][3] += dt * P[r][4] + hd2 * P[r][5];
            P[r][4] += dt * P[r][5];
        }
#pragma unroll
        for (int i = 0; i < 6; i++)
#pragma unroll
            for (int j = 0; j < 6; j++) P[i][j] += Gs[i] * Gs[j];

        // outputs: mu_x, mu_y, sx, sy, rho
        float sx = sqrtf(P[0][0]);
        float sy = sqrtf(P[3][3]);
        float rho = (P[0][3] + P[3][0]) / (2.0f * sx * sy);
        size_t o = ((size_t)t * B + b) * 5;
        out[o + 0] = X[0];
        out[o + 1] = X[3];
        out[o + 2] = sx;
        out[o + 3] = sy;
        out[o + 4] = rho;
    }
}

extern "C" void kernel_launch(void* const* d_in, const int* in_sizes, int n_in,
                              void* d_out, int out_size) {
    const float* hist  = (const float*)d_in[0];
    const float* psx   = (const float*)d_in[1];
    const float* psy   = (const float*)d_in[2];
    const float* vsx   = (const float*)d_in[3];
    const float* vsy   = (const float*)d_in[4];
    const float* asx   = (const float*)d_in[5];
    const float* asy   = (const float*)d_in[6];
    const float* jerk  = (const float*)d_in[7];
    const float* coefG = (const float*)d_in[8];
    const float* GR    = (const float*)d_in[9];
    const float* cfW   = (const float*)d_in[10];
    const float* cfb   = (const float*)d_in[11];
    const float* Wih   = (const float*)d_in[12];
    const float* Whh   = (const float*)d_in[13];
    const float* bih   = (const float*)d_in[14];
    const float* bhh   = (const float*)d_in[15];
    const float* coW   = (const float*)d_in[16];
    const float* cob   = (const float*)d_in[17];
    float* out = (float*)d_out;

    const int T = 16;
    int B  = in_sizes[0] / (2 * T);
    int LP = out_size / (B * 5);

    size_t smem = (size_t)(8720 + 64 * TB) * sizeof(float);  // 67648 bytes
    cudaFuncSetAttribute(kalman_lstm_kernel,
                         cudaFuncAttributeMaxDynamicSharedMemorySize, (int)smem);

    int grid = (B + TB - 1) / TB;
    kalman_lstm_kernel<<<grid, TB, smem>>>(
        hist, psx, psy, vsx, vsy, asx, asy, jerk, coefG, GR,
        cfW, cfb, Wih, Whh, bih, bhh, coW, cob, out, B, T, LP);
}